// round 10
// baseline (speedup 1.0000x reference)
#include <cuda_runtime.h>
#include <cuda_fp16.h>
#include <cstdint>

// Problem constants
#define Bc   1024
#define Tc   512
#define EMBc 100
#define KP   112   // padded K for layer-1 gemm (fp16, zero-filled)
#define H1c  128
#define G1c  512   // 4*H1
#define H2c  64
#define G2c  256   // 4*H2
#define Mtot (Bc*Tc)  // 524288

// Scratch (fp16)
__device__ __half g_xh [(size_t)Mtot * KP];    // padded fp16 X
__device__ __half g_w1h[(size_t)G1c * KP];     // padded fp16 W1_ih
__device__ __half g_xw1[(size_t)Mtot * G1c];   // PERMUTED: [bblk][t][gate][8]
__device__ __half g_hs1[(size_t)Mtot * H1c];   // layer-1 hidden states [b][t][128]

// ---------------------------------------------------------------------------
// helpers
// ---------------------------------------------------------------------------
__device__ __forceinline__ uint32_t s2u(const void* p) {
    return (uint32_t)__cvta_generic_to_shared(p);
}
__device__ __forceinline__ void ldm_x4(uint32_t& a0, uint32_t& a1, uint32_t& a2, uint32_t& a3,
                                       uint32_t addr) {
    asm volatile("ldmatrix.sync.aligned.m8n8.x4.shared.b16 {%0,%1,%2,%3}, [%4];"
                 : "=r"(a0), "=r"(a1), "=r"(a2), "=r"(a3) : "r"(addr));
}
__device__ __forceinline__ void ldm_x2(uint32_t& b0, uint32_t& b1, uint32_t addr) {
    asm volatile("ldmatrix.sync.aligned.m8n8.x2.shared.b16 {%0,%1}, [%2];"
                 : "=r"(b0), "=r"(b1) : "r"(addr));
}
__device__ __forceinline__ void mma16816(float* d, const uint32_t* a, const uint32_t* b) {
    asm volatile("mma.sync.aligned.m16n8k16.row.col.f32.f16.f16.f32 "
                 "{%0,%1,%2,%3}, {%4,%5,%6,%7}, {%8,%9}, {%0,%1,%2,%3};"
                 : "+f"(d[0]), "+f"(d[1]), "+f"(d[2]), "+f"(d[3])
                 : "r"(a[0]), "r"(a[1]), "r"(a[2]), "r"(a[3]), "r"(b[0]), "r"(b[1]));
}
__device__ __forceinline__ float tanhfast(float x) {
    float y;
    asm("tanh.approx.f32 %0, %1;" : "=f"(y) : "f"(x));
    return y;
}
__device__ __forceinline__ float sigfast(float x) {
    return 0.5f * tanhfast(0.5f * x) + 0.5f;
}
__device__ __forceinline__ uint32_t packh2(float x, float y) {
    __half2 h = __floats2half2_rn(x, y);
    return *reinterpret_cast<uint32_t*>(&h);
}
__device__ __forceinline__ void cp16(uint32_t smem_addr, const void* gptr) {
    asm volatile("cp.async.cg.shared.global [%0], [%1], 16;" :: "r"(smem_addr), "l"(gptr));
}
__device__ __forceinline__ void cp_commit() { asm volatile("cp.async.commit_group;"); }
__device__ __forceinline__ void cp_wait0()  { asm volatile("cp.async.wait_group 0;"); }

// ---------------------------------------------------------------------------
// fp32 [rows][EMBc] -> fp16 [rows][KP], zero-padded.
// ---------------------------------------------------------------------------
__global__ void convert_pad(const float* __restrict__ src, __half* __restrict__ dst, int rows)
{
    int gid = blockIdx.x * blockDim.x + threadIdx.x;
    int total = rows * (KP / 2);
    if (gid >= total) return;
    int row = gid / (KP / 2);
    int p   = gid - row * (KP / 2);
    int k   = 2 * p;
    float x0 = (k < EMBc)     ? src[(size_t)row * EMBc + k]     : 0.f;
    float x1 = (k + 1 < EMBc) ? src[(size_t)row * EMBc + k + 1] : 0.f;
    *(__half2*)(dst + (size_t)row * KP + k) = __floats2half2_rn(x0, x1);
}

// ---------------------------------------------------------------------------
// Layer-1 GEMM, fp16 in / fp16 out, K=112 single smem tile.
// Output PERMUTED: xw1p[(b>>3)*512 + t][gate*8 + (b&7)] (+bias).
// BM=128 (one b, 128 t's), BN=128 gates, 256 threads.
// ---------------------------------------------------------------------------
__global__ void __launch_bounds__(256) gemm1h(const __half* __restrict__ A,   // [M][112]
                                              const __half* __restrict__ W,   // [512][112]
                                              const float* __restrict__ ba,
                                              const float* __restrict__ bb,
                                              __half* __restrict__ outp)
{
    constexpr int LDSs = 120;
    __shared__ alignas(16) __half As[128 * LDSs];
    __shared__ alignas(16) __half Ws[128 * LDSs];

    const int tid  = threadIdx.x;
    const int bm   = blockIdx.y * 128;
    const int bn   = blockIdx.x * 128;
    const int w    = tid >> 5;
    const int lane = tid & 31;
    const int wm   = (w >> 2) * 64;
    const int wn   = (w & 3) * 32;

    {
        const int m = tid >> 1;
#pragma unroll
        for (int c = 0; c < 7; c++) {
            int cc = c * 2 + (tid & 1);
            cp16(s2u(&As[m * LDSs + cc * 8]), A + (size_t)(bm + m) * KP + cc * 8);
            cp16(s2u(&Ws[m * LDSs + cc * 8]), W + (size_t)(bn + m) * KP + cc * 8);
        }
        cp_commit();
        cp_wait0();
    }
    __syncthreads();

    float acc[4][4][4];
#pragma unroll
    for (int mt = 0; mt < 4; mt++)
#pragma unroll
        for (int nt = 0; nt < 4; nt++)
#pragma unroll
            for (int i = 0; i < 4; i++) acc[mt][nt][i] = 0.f;

#pragma unroll
    for (int ks = 0; ks < 7; ks++) {
        uint32_t af[4][4];
#pragma unroll
        for (int mt = 0; mt < 4; mt++) {
            uint32_t addr = s2u(&As[(wm + mt * 16 + (lane & 15)) * LDSs + ks * 16 + (lane >> 4) * 8]);
            ldm_x4(af[mt][0], af[mt][1], af[mt][2], af[mt][3], addr);
        }
        uint32_t bf[4][2];
#pragma unroll
        for (int nt = 0; nt < 4; nt++) {
            int l = lane & 15;
            uint32_t addr = s2u(&Ws[(wn + nt * 8 + (l & 7)) * LDSs + ks * 16 + ((l >> 3) & 1) * 8]);
            ldm_x2(bf[nt][0], bf[nt][1], addr);
        }
#pragma unroll
        for (int mt = 0; mt < 4; mt++)
#pragma unroll
            for (int nt = 0; nt < 4; nt++)
                mma16816(acc[mt][nt], af[mt], bf[nt]);
    }

    // permuted scatter epilogue
#pragma unroll
    for (int mt = 0; mt < 4; mt++) {
#pragma unroll
        for (int nt = 0; nt < 4; nt++) {
            int m0  = bm + wm + mt * 16 + (lane >> 2);   // = b*512 + t
            int col = bn + wn + nt * 8 + (lane & 3) * 2;
            float b0 = __ldg(ba + col) + __ldg(bb + col);
            float b1 = __ldg(ba + col + 1) + __ldg(bb + col + 1);
            int b  = m0 >> 9, t0 = m0 & 511;
            int bi = b & 7;
            size_t base0 = ((size_t)(b >> 3) * 512 + t0) * (G1c * 8);
            size_t base1 = base0 + 8 * (size_t)(G1c * 8);   // row m0+8 -> t0+8, same b
            outp[base0 + (size_t)col * 8 + bi]       = __float2half_rn(acc[mt][nt][0] + b0);
            outp[base0 + (size_t)(col + 1) * 8 + bi] = __float2half_rn(acc[mt][nt][1] + b1);
            outp[base1 + (size_t)col * 8 + bi]       = __float2half_rn(acc[mt][nt][2] + b0);
            outp[base1 + (size_t)(col + 1) * 8 + bi] = __float2half_rn(acc[mt][nt][3] + b1);
        }
    }
}

// ---------------------------------------------------------------------------
// LSTM layer 1: gate-permuted tensor-core recurrence.
// - xw tile: ONE contiguous 8KB cp.async per step (permuted layout)
// - acc init: vectorized half2 LDS (4/thread)
// - MMA: 4 independent 4-chains
// - hs1: staged in smem, coalesced STG.128 next step
// ---------------------------------------------------------------------------
__global__ void __launch_bounds__(512) lstm1_kernel(const __half* __restrict__ xwp,  // [bblk][t][512][8]
                                                    const float* __restrict__ Whh,   // [512][128]
                                                    __half* __restrict__ hs1)        // [B][T][128]
{
    constexpr int HP1 = 136;
    __shared__ __half hsh[2][8 * HP1];
    __shared__ alignas(16) __half xs[2][G1c * 8];      // 16KB
    __shared__ alignas(16) __half hstage[2][8 * 128];  // 4KB

    const int tid  = threadIdx.x;
    const int w    = tid >> 5;
    const int lane = tid & 31;
    const int bblk = blockIdx.x;
    const int b0   = bblk * 8;
    const int r    = lane >> 2;
    const int q    = lane & 3;
    const int n0   = q * 2;
    const bool lo  = (r < 4);

    int uu[2], Glo[2], Ghi[2];
#pragma unroll
    for (int mt = 0; mt < 2; mt++) {
        uu[mt]  = w * 8 + mt * 4 + (r & 3);
        Glo[mt] = (r >> 2) * H1c + uu[mt];
        Ghi[mt] = ((r + 8) >> 2) * H1c + uu[mt];
    }

    uint32_t afr[2][8][4];
#pragma unroll
    for (int mt = 0; mt < 2; mt++) {
        const float* rl = Whh + (size_t)Glo[mt] * H1c;
        const float* rh = Whh + (size_t)Ghi[mt] * H1c;
#pragma unroll
        for (int ks = 0; ks < 8; ks++) {
            int k = ks * 16 + q * 2;
            afr[mt][ks][0] = packh2(rl[k],     rl[k + 1]);
            afr[mt][ks][1] = packh2(rh[k],     rh[k + 1]);
            afr[mt][ks][2] = packh2(rl[k + 8], rl[k + 9]);
            afr[mt][ks][3] = packh2(rh[k + 8], rh[k + 9]);
        }
    }

    for (int i = tid; i < 2 * 8 * HP1 / 2; i += 512)
        ((__half2*)hsh)[i] = __floats2half2_rn(0.f, 0.f);

    const __half* xg = xwp + (size_t)bblk * Tc * (G1c * 8);
    // prefetch xw tile t=0 (contiguous 8KB: 512 threads x 16B)
    cp16(s2u(&xs[0][tid * 8]), xg + (size_t)0 * (G1c * 8) + tid * 8);
    cp_commit();
    cp_wait0();
    __syncthreads();

    const int ncol = n0 + (lo ? 0 : 1);
    float cst[2] = {0.f, 0.f};

    for (int t = 0; t < Tc; t++) {
        // prefetch next tile
        if (t + 1 < Tc) {
            cp16(s2u(&xs[(t + 1) & 1][tid * 8]), xg + (size_t)(t + 1) * (G1c * 8) + tid * 8);
            cp_commit();
        }
        // coalesced flush of h_{t-1} to hs1
        if (t > 0 && tid < 128) {
            int row = tid >> 4, ch = tid & 15;
            uint4 v = *(const uint4*)&hstage[(t - 1) & 1][row * 128 + ch * 8];
            *(uint4*)(hs1 + ((size_t)(b0 + row) * Tc + (t - 1)) * H1c + ch * 8) = v;
        }

        const __half* hb = hsh[t & 1];
        const __half2* x2 = (const __half2*)xs[t & 1];

        uint32_t bf[8][2];
        {
            const int l = lane & 15;
            uint32_t baddr = s2u(&hb[(l & 7) * HP1 + ((l >> 3) & 1) * 8]);
#pragma unroll
            for (int ks = 0; ks < 8; ks++)
                ldm_x2(bf[ks][0], bf[ks][1], baddr + ks * 32);
        }

        // acc init (vectorized) + 4 independent 4-chains
        float2 xl0 = __half22float2(x2[Glo[0] * 4 + q]);
        float2 xh0 = __half22float2(x2[Ghi[0] * 4 + q]);
        float2 xl1 = __half22float2(x2[Glo[1] * 4 + q]);
        float2 xh1 = __half22float2(x2[Ghi[1] * 4 + q]);
        float A0[4] = {xl0.x, xl0.y, xh0.x, xh0.y};
        float B0[4] = {0.f, 0.f, 0.f, 0.f};
        float A1[4] = {xl1.x, xl1.y, xh1.x, xh1.y};
        float B1[4] = {0.f, 0.f, 0.f, 0.f};
#pragma unroll
        for (int ks = 0; ks < 4; ks++) {
            mma16816(A0, afr[0][ks], bf[ks]);
            mma16816(A1, afr[1][ks], bf[ks]);
            mma16816(B0, afr[0][ks + 4], bf[ks + 4]);
            mma16816(B1, afr[1][ks + 4], bf[ks + 4]);
        }
        float acc[2][4];
#pragma unroll
        for (int i = 0; i < 4; i++) { acc[0][i] = A0[i] + B0[i]; acc[1][i] = A1[i] + B1[i]; }

#pragma unroll
        for (int mt = 0; mt < 2; mt++) {
            float s0 = lo ? acc[mt][1] : acc[mt][0];
            float s1 = lo ? acc[mt][3] : acc[mt][2];
            float r0 = __shfl_xor_sync(0xffffffffu, s0, 16);
            float r1 = __shfl_xor_sync(0xffffffffu, s1, 16);
            float zi = lo ? acc[mt][0] : r0;
            float zf = lo ? r0         : acc[mt][1];
            float zg = lo ? acc[mt][2] : r1;
            float zo = lo ? r1         : acc[mt][3];

            cst[mt] = sigfast(zf) * cst[mt] + sigfast(zi) * tanhfast(zg);
            float h = sigfast(zo) * tanhfast(cst[mt]);

            __half hh = __float2half_rn(h);
            hsh[(t + 1) & 1][ncol * HP1 + uu[mt]] = hh;
            hstage[t & 1][ncol * 128 + uu[mt]] = hh;
        }
        cp_wait0();
        __syncthreads();
    }
    // flush last step
    if (tid < 128) {
        int row = tid >> 4, ch = tid & 15;
        uint4 v = *(const uint4*)&hstage[(Tc - 1) & 1][row * 128 + ch * 8];
        *(uint4*)(hs1 + ((size_t)(b0 + row) * Tc + (Tc - 1)) * H1c + ch * 8) = v;
    }
}

// ---------------------------------------------------------------------------
// LSTM layer 2 (gate-permuted, fused input projection) + FC head.
// 3 independent MMA chains (bias+ih0-3 / ih4-7 / hh0-3).
// ---------------------------------------------------------------------------
__global__ void __launch_bounds__(512) lstm2_kernel(const __half* __restrict__ hs1,  // [B][T][128]
                                                    const float* __restrict__ Whh,   // [256][64]
                                                    const float* __restrict__ Wih,   // [256][128]
                                                    const float* __restrict__ b_ih,
                                                    const float* __restrict__ b_hh,
                                                    const float* __restrict__ fc1w,
                                                    const float* __restrict__ fc1b,
                                                    const float* __restrict__ fc2w,
                                                    const float* __restrict__ fc2b,
                                                    float* __restrict__ out)
{
    constexpr int HP = 72;
    constexpr int XP = 136;
    __shared__ __half hsh[2][8 * HP];
    __shared__ alignas(16) __half xb[2][8 * XP];
    __shared__ float hfin[8][64];

    const int tid  = threadIdx.x;
    const int w    = tid >> 5;
    const int lane = tid & 31;
    const int b0   = blockIdx.x * 8;
    const int r    = lane >> 2;
    const int q    = lane & 3;
    const int n0   = q * 2;
    const bool lo  = (r < 4);

    const int u   = w * 4 + (r & 3);
    const int Glo = (r >> 2) * H2c + u;
    const int Ghi = ((r + 8) >> 2) * H2c + u;

    uint32_t ahh[4][4];
    {
        const float* rl = Whh + (size_t)Glo * H2c;
        const float* rh = Whh + (size_t)Ghi * H2c;
#pragma unroll
        for (int ks = 0; ks < 4; ks++) {
            int k = ks * 16 + q * 2;
            ahh[ks][0] = packh2(rl[k],     rl[k + 1]);
            ahh[ks][1] = packh2(rh[k],     rh[k + 1]);
            ahh[ks][2] = packh2(rl[k + 8], rl[k + 9]);
            ahh[ks][3] = packh2(rh[k + 8], rh[k + 9]);
        }
    }
    uint32_t aih[8][4];
    {
        const float* rl = Wih + (size_t)Glo * H1c;
        const float* rh = Wih + (size_t)Ghi * H1c;
#pragma unroll
        for (int ks = 0; ks < 8; ks++) {
            int k = ks * 16 + q * 2;
            aih[ks][0] = packh2(rl[k],     rl[k + 1]);
            aih[ks][1] = packh2(rh[k],     rh[k + 1]);
            aih[ks][2] = packh2(rl[k + 8], rl[k + 9]);
            aih[ks][3] = packh2(rh[k + 8], rh[k + 9]);
        }
    }
    const float blo = __ldg(b_ih + Glo) + __ldg(b_hh + Glo);
    const float bhi = __ldg(b_ih + Ghi) + __ldg(b_hh + Ghi);

    for (int i = tid; i < 2 * 8 * HP / 2; i += 512)
        ((__half2*)hsh)[i] = __floats2half2_rn(0.f, 0.f);

    if (tid < 128) {
        int row = tid >> 4, ch = tid & 15;
        cp16(s2u(&xb[0][row * XP + ch * 8]),
             hs1 + ((size_t)(b0 + row) * Tc + 0) * H1c + ch * 8);
        cp_commit();
        cp_wait0();
    }
    __syncthreads();

    const int ncol = n0 + (lo ? 0 : 1);
    float cst = 0.f;

    for (int t = 0; t < Tc; t++) {
        if (tid < 128 && t + 1 < Tc) {
            int row = tid >> 4, ch = tid & 15;
            cp16(s2u(&xb[(t + 1) & 1][row * XP + ch * 8]),
                 hs1 + ((size_t)(b0 + row) * Tc + (t + 1)) * H1c + ch * 8);
            cp_commit();
        }

        const __half* x1 = xb[t & 1];
        const __half* hb = hsh[t & 1];
        const int l = lane & 15;

        uint32_t bh1[8][2];
        {
            uint32_t baddr = s2u(&x1[(l & 7) * XP + ((l >> 3) & 1) * 8]);
#pragma unroll
            for (int ks = 0; ks < 8; ks++)
                ldm_x2(bh1[ks][0], bh1[ks][1], baddr + ks * 32);
        }
        uint32_t bh2[4][2];
        {
            uint32_t baddr = s2u(&hb[(l & 7) * HP + ((l >> 3) & 1) * 8]);
#pragma unroll
            for (int ks = 0; ks < 4; ks++)
                ldm_x2(bh2[ks][0], bh2[ks][1], baddr + ks * 32);
        }

        float A[4] = {blo, blo, bhi, bhi};
        float B[4] = {0.f, 0.f, 0.f, 0.f};
        float C[4] = {0.f, 0.f, 0.f, 0.f};
#pragma unroll
        for (int ks = 0; ks < 4; ks++) {
            mma16816(A, aih[ks], bh1[ks]);
            mma16816(B, aih[ks + 4], bh1[ks + 4]);
            mma16816(C, ahh[ks], bh2[ks]);
        }
        float acc[4];
#pragma unroll
        for (int i = 0; i < 4; i++) acc[i] = A[i] + B[i] + C[i];

        float s0 = lo ? acc[1] : acc[0];
        float s1 = lo ? acc[3] : acc[2];
        float r0 = __shfl_xor_sync(0xffffffffu, s0, 16);
        float r1 = __shfl_xor_sync(0xffffffffu, s1, 16);
        float zi = lo ? acc[0] : r0;
        float zf = lo ? r0     : acc[1];
        float zg = lo ? acc[2] : r1;
        float zo = lo ? r1     : acc[3];

        cst = sigfast(zf) * cst + sigfast(zi) * tanhfast(zg);
        float h = sigfast(zo) * tanhfast(cst);

        hsh[(t + 1) & 1][ncol * HP + u] = __float2half_rn(h);
        if (t == Tc - 1) hfin[ncol][u] = h;

        if (tid < 128) cp_wait0();
        __syncthreads();
    }

    // FC head
    if (w < 8) {
        float a = __ldg(fc1b + lane);
#pragma unroll
        for (int k = 0; k < 64; k++)
            a = fmaf(hfin[w][k], __ldg(fc1w + lane * 64 + k), a);
        a = fmaxf(a, 0.f);
        float v = a * __ldg(fc2w + lane);
#pragma unroll
        for (int off = 16; off; off >>= 1) v += __shfl_down_sync(0xffffffffu, v, off);
        if (lane == 0) out[b0 + w] = 1.f / (1.f + __expf(-(v + __ldg(fc2b))));
    }
}

// ---------------------------------------------------------------------------
extern "C" void kernel_launch(void* const* d_in, const int* in_sizes, int n_in,
                              void* d_out, int out_size)
{
    (void)in_sizes; (void)n_in; (void)out_size;
    const float* X     = (const float*)d_in[0];
    const float* W1_ih = (const float*)d_in[1];
    const float* W1_hh = (const float*)d_in[2];
    const float* b1_ih = (const float*)d_in[3];
    const float* b1_hh = (const float*)d_in[4];
    const float* W2_ih = (const float*)d_in[5];
    const float* W2_hh = (const float*)d_in[6];
    const float* b2_ih = (const float*)d_in[7];
    const float* b2_hh = (const float*)d_in[8];
    const float* fc1w  = (const float*)d_in[9];
    const float* fc1b  = (const float*)d_in[10];
    const float* fc2w  = (const float*)d_in[11];
    const float* fc2b  = (const float*)d_in[12];
    float* out = (float*)d_out;

    __half *xh, *w1h, *xw1, *hs1;
    cudaGetSymbolAddress((void**)&xh,  g_xh);
    cudaGetSymbolAddress((void**)&w1h, g_w1h);
    cudaGetSymbolAddress((void**)&xw1, g_xw1);
    cudaGetSymbolAddress((void**)&hs1, g_hs1);

    // 0) pad+convert X and W1_ih to fp16 [..][112]
    convert_pad<<<(Mtot * (KP / 2) + 255) / 256, 256>>>(X, xh, Mtot);
    convert_pad<<<(G1c * (KP / 2) + 255) / 256, 256>>>(W1_ih, w1h, G1c);
    // 1) xw1p = half(X @ W1_ih^T + b), permuted [bblk][t][gate][8]
    gemm1h<<<dim3(G1c / 128, Mtot / 128), 256>>>(xh, w1h, b1_ih, b1_hh, xw1);
    // 2) layer-1 recurrence
    lstm1_kernel<<<Bc / 8, 512>>>(xw1, W1_hh, hs1);
    // 3) layer-2 recurrence (fused input projection) + FC head
    lstm2_kernel<<<Bc / 8, 512>>>(hs1, W2_hh, W2_ih, b2_ih, b2_hh,
                                  fc1w, fc1b, fc2w, fc2b, out);
}

// round 11
// speedup vs baseline: 2.7761x; 2.7761x over previous
#include <cuda_runtime.h>
#include <cuda_fp16.h>
#include <cstdint>

// Problem constants
#define Bc   1024
#define Tc   512
#define EMBc 100
#define KP   112   // padded K for layer-1 gemm (fp16, zero-filled)
#define H1c  128
#define G1c  512   // 4*H1
#define H2c  64
#define G2c  256   // 4*H2
#define Mtot (Bc*Tc)  // 524288

// Scratch (fp16)
__device__ __half g_xh [(size_t)Mtot * KP];   // padded fp16 X
__device__ __half g_w1h[(size_t)G1c * KP];    // padded fp16 W1_ih
__device__ __half g_xw1[(size_t)Mtot * G1c];  // layer-1 gate preactivations [b][t][512]
__device__ __half g_hs1[(size_t)Mtot * H1c];  // layer-1 hidden states [b][t][128]

// ---------------------------------------------------------------------------
// helpers
// ---------------------------------------------------------------------------
__device__ __forceinline__ uint32_t s2u(const void* p) {
    return (uint32_t)__cvta_generic_to_shared(p);
}
__device__ __forceinline__ void ldm_x4(uint32_t& a0, uint32_t& a1, uint32_t& a2, uint32_t& a3,
                                       uint32_t addr) {
    asm volatile("ldmatrix.sync.aligned.m8n8.x4.shared.b16 {%0,%1,%2,%3}, [%4];"
                 : "=r"(a0), "=r"(a1), "=r"(a2), "=r"(a3) : "r"(addr));
}
__device__ __forceinline__ void ldm_x2(uint32_t& b0, uint32_t& b1, uint32_t addr) {
    asm volatile("ldmatrix.sync.aligned.m8n8.x2.shared.b16 {%0,%1}, [%2];"
                 : "=r"(b0), "=r"(b1) : "r"(addr));
}
__device__ __forceinline__ void mma16816(float* d, const uint32_t* a, const uint32_t* b) {
    asm volatile("mma.sync.aligned.m16n8k16.row.col.f32.f16.f16.f32 "
                 "{%0,%1,%2,%3}, {%4,%5,%6,%7}, {%8,%9}, {%0,%1,%2,%3};"
                 : "+f"(d[0]), "+f"(d[1]), "+f"(d[2]), "+f"(d[3])
                 : "r"(a[0]), "r"(a[1]), "r"(a[2]), "r"(a[3]), "r"(b[0]), "r"(b[1]));
}
__device__ __forceinline__ float tanhfast(float x) {
    float y;
    asm("tanh.approx.f32 %0, %1;" : "=f"(y) : "f"(x));
    return y;
}
__device__ __forceinline__ float sigfast(float x) {
    return 0.5f * tanhfast(0.5f * x) + 0.5f;
}
__device__ __forceinline__ uint32_t packh2(float x, float y) {
    __half2 h = __floats2half2_rn(x, y);
    return *reinterpret_cast<uint32_t*>(&h);
}
__device__ __forceinline__ void cp16(uint32_t smem_addr, const void* gptr) {
    asm volatile("cp.async.cg.shared.global [%0], [%1], 16;" :: "r"(smem_addr), "l"(gptr));
}
__device__ __forceinline__ void cp_commit() { asm volatile("cp.async.commit_group;"); }
__device__ __forceinline__ void cp_wait0()  { asm volatile("cp.async.wait_group 0;"); }

// ---------------------------------------------------------------------------
// fp32 [rows][EMBc] -> fp16 [rows][KP], zero-padded.
// ---------------------------------------------------------------------------
__global__ void convert_pad(const float* __restrict__ src, __half* __restrict__ dst, int rows)
{
    int gid = blockIdx.x * blockDim.x + threadIdx.x;
    int total = rows * (KP / 2);
    if (gid >= total) return;
    int row = gid / (KP / 2);
    int p   = gid - row * (KP / 2);
    int k   = 2 * p;
    float x0 = (k < EMBc)     ? src[(size_t)row * EMBc + k]     : 0.f;
    float x1 = (k + 1 < EMBc) ? src[(size_t)row * EMBc + k + 1] : 0.f;
    *(__half2*)(dst + (size_t)row * KP + k) = __floats2half2_rn(x0, x1);
}

// ---------------------------------------------------------------------------
// Layer-1 GEMM (R9 known-good): fp16 in / fp16 out, K=112 single smem tile.
// out[m][n] = half(sum_k A[m][k]*W[n][k] + ba[n] + bb[n]), row-major out.
// ---------------------------------------------------------------------------
__global__ void __launch_bounds__(256) gemm1h(const __half* __restrict__ A,   // [M][112]
                                              const __half* __restrict__ W,   // [512][112]
                                              const float* __restrict__ ba,
                                              const float* __restrict__ bb,
                                              __half* __restrict__ out)
{
    constexpr int LDSs = 120;
    __shared__ alignas(16) __half As[128 * LDSs];
    __shared__ alignas(16) __half Ws[128 * LDSs];

    const int tid  = threadIdx.x;
    const int bm   = blockIdx.y * 128;
    const int bn   = blockIdx.x * 128;
    const int w    = tid >> 5;
    const int lane = tid & 31;
    const int wm   = (w >> 2) * 64;
    const int wn   = (w & 3) * 32;

    {
        const int m = tid >> 1;
#pragma unroll
        for (int c = 0; c < 7; c++) {
            int cc = c * 2 + (tid & 1);
            cp16(s2u(&As[m * LDSs + cc * 8]), A + (size_t)(bm + m) * KP + cc * 8);
            cp16(s2u(&Ws[m * LDSs + cc * 8]), W + (size_t)(bn + m) * KP + cc * 8);
        }
        cp_commit();
        cp_wait0();
    }
    __syncthreads();

    float acc[4][4][4];
#pragma unroll
    for (int mt = 0; mt < 4; mt++)
#pragma unroll
        for (int nt = 0; nt < 4; nt++)
#pragma unroll
            for (int i = 0; i < 4; i++) acc[mt][nt][i] = 0.f;

#pragma unroll
    for (int ks = 0; ks < 7; ks++) {
        uint32_t af[4][4];
#pragma unroll
        for (int mt = 0; mt < 4; mt++) {
            uint32_t addr = s2u(&As[(wm + mt * 16 + (lane & 15)) * LDSs + ks * 16 + (lane >> 4) * 8]);
            ldm_x4(af[mt][0], af[mt][1], af[mt][2], af[mt][3], addr);
        }
        uint32_t bf[4][2];
#pragma unroll
        for (int nt = 0; nt < 4; nt++) {
            int l = lane & 15;
            uint32_t addr = s2u(&Ws[(wn + nt * 8 + (l & 7)) * LDSs + ks * 16 + ((l >> 3) & 1) * 8]);
            ldm_x2(bf[nt][0], bf[nt][1], addr);
        }
#pragma unroll
        for (int mt = 0; mt < 4; mt++)
#pragma unroll
            for (int nt = 0; nt < 4; nt++)
                mma16816(acc[mt][nt], af[mt], bf[nt]);
    }

#pragma unroll
    for (int mt = 0; mt < 4; mt++) {
#pragma unroll
        for (int nt = 0; nt < 4; nt++) {
            int row = bm + wm + mt * 16 + (lane >> 2);
            int col = bn + wn + nt * 8 + (lane & 3) * 2;
            float b0 = __ldg(ba + col) + __ldg(bb + col);
            float b1 = __ldg(ba + col + 1) + __ldg(bb + col + 1);
            *(__half2*)(out + (size_t)row * G1c + col) =
                __floats2half2_rn(acc[mt][nt][0] + b0, acc[mt][nt][1] + b1);
            *(__half2*)(out + (size_t)(row + 8) * G1c + col) =
                __floats2half2_rn(acc[mt][nt][2] + b0, acc[mt][nt][3] + b1);
        }
    }
}

// ---------------------------------------------------------------------------
// LSTM layer 1: gate-permuted tensor-core recurrence (R9 base).
// R11 deltas: early hoisted xw scalar loads, interleaved mt0/mt1 MMA chains,
// coalesced hs1 stores via hstage smem staging.
// ---------------------------------------------------------------------------
__global__ void __launch_bounds__(512) lstm1_kernel(const __half* __restrict__ xw,   // [B][T][512]
                                                    const float* __restrict__ Whh,   // [512][128]
                                                    __half* __restrict__ hs1)        // [B][T][128]
{
    constexpr int HP1 = 136;
    constexpr int XP = 520;    // padded xw row (halves)
    __shared__ __half hsh[2][8 * HP1];
    __shared__ alignas(16) __half xwb[2][8 * XP];
    __shared__ alignas(16) __half hstage[2][8 * 128];

    const int tid  = threadIdx.x;
    const int w    = tid >> 5;
    const int lane = tid & 31;
    const int b0   = blockIdx.x * 8;
    const int r    = lane >> 2;
    const int q    = lane & 3;
    const int n0   = q * 2;
    const bool lo  = (r < 4);

    // permuted row mapping
    int uu[2], Glo[2], Ghi[2];
#pragma unroll
    for (int mt = 0; mt < 2; mt++) {
        uu[mt]  = w * 8 + mt * 4 + (r & 3);
        Glo[mt] = (r >> 2) * H1c + uu[mt];          // gate 0/1 (i or f)
        Ghi[mt] = ((r + 8) >> 2) * H1c + uu[mt];    // gate 2/3 (g or o)
    }

    // persistent A fragments (permuted W_hh rows, fp16)
    uint32_t afr[2][8][4];
#pragma unroll
    for (int mt = 0; mt < 2; mt++) {
        const float* rl = Whh + (size_t)Glo[mt] * H1c;
        const float* rh = Whh + (size_t)Ghi[mt] * H1c;
#pragma unroll
        for (int ks = 0; ks < 8; ks++) {
            int k = ks * 16 + q * 2;
            afr[mt][ks][0] = packh2(rl[k],     rl[k + 1]);
            afr[mt][ks][1] = packh2(rh[k],     rh[k + 1]);
            afr[mt][ks][2] = packh2(rl[k + 8], rl[k + 9]);
            afr[mt][ks][3] = packh2(rh[k + 8], rh[k + 9]);
        }
    }

    // zero h state (both buffers)
    for (int i = tid; i < 2 * 8 * HP1 / 2; i += 512)
        ((__half2*)hsh)[i] = __floats2half2_rn(0.f, 0.f);

    // prefetch xw tile for t=0 (8 rows x 64 16B chunks)
    {
        int row = tid >> 6, ch = tid & 63;
        cp16(s2u(&xwb[0][row * XP + ch * 8]),
             xw + ((size_t)(b0 + row) * Tc + 0) * G1c + ch * 8);
        cp_commit();
        cp_wait0();
    }
    __syncthreads();

    const int ncol = n0 + (lo ? 0 : 1);
    float cst[2] = {0.f, 0.f};

    for (int t = 0; t < Tc; t++) {
        // prefetch xw tile for t+1
        if (t + 1 < Tc) {
            int row = tid >> 6, ch = tid & 63;
            cp16(s2u(&xwb[(t + 1) & 1][row * XP + ch * 8]),
                 xw + ((size_t)(b0 + row) * Tc + (t + 1)) * G1c + ch * 8);
            cp_commit();
        }
        // coalesced flush of h_{t-1} to hs1 (written before last barrier)
        if (t > 0 && tid < 128) {
            int row = tid >> 4, ch = tid & 15;
            uint4 v = *(const uint4*)&hstage[(t - 1) & 1][row * 128 + ch * 8];
            *(uint4*)(hs1 + ((size_t)(b0 + row) * Tc + (t - 1)) * H1c + ch * 8) = v;
        }

        const __half* xb = xwb[t & 1];
        const __half* hb = hsh[t & 1];

        // early xw acc-init loads (latency overlapped with ldmatrix+MMA below)
        float xa0 = __half2float(xb[n0 * XP + Glo[0]]);
        float xa1 = __half2float(xb[(n0 + 1) * XP + Glo[0]]);
        float xa2 = __half2float(xb[n0 * XP + Ghi[0]]);
        float xa3 = __half2float(xb[(n0 + 1) * XP + Ghi[0]]);
        float xb0 = __half2float(xb[n0 * XP + Glo[1]]);
        float xb1 = __half2float(xb[(n0 + 1) * XP + Glo[1]]);
        float xb2 = __half2float(xb[n0 * XP + Ghi[1]]);
        float xb3 = __half2float(xb[(n0 + 1) * XP + Ghi[1]]);

        // B fragments: h_{t-1}
        uint32_t bf[8][2];
        {
            const int l = lane & 15;
            uint32_t baddr = s2u(&hb[(l & 7) * HP1 + ((l >> 3) & 1) * 8]);
#pragma unroll
            for (int ks = 0; ks < 8; ks++)
                ldm_x2(bf[ks][0], bf[ks][1], baddr + ks * 32);
        }

        // two interleaved 8-MMA chains (mt0 / mt1)
        float acc[2][4];
        acc[0][0] = xa0; acc[0][1] = xa1; acc[0][2] = xa2; acc[0][3] = xa3;
        acc[1][0] = xb0; acc[1][1] = xb1; acc[1][2] = xb2; acc[1][3] = xb3;
#pragma unroll
        for (int ks = 0; ks < 8; ks++) {
            mma16816(acc[0], afr[0][ks], bf[ks]);
            mma16816(acc[1], afr[1][ks], bf[ks]);
        }

#pragma unroll
        for (int mt = 0; mt < 2; mt++) {
            float s0 = lo ? acc[mt][1] : acc[mt][0];
            float s1 = lo ? acc[mt][3] : acc[mt][2];
            float r0 = __shfl_xor_sync(0xffffffffu, s0, 16);
            float r1 = __shfl_xor_sync(0xffffffffu, s1, 16);
            float zi = lo ? acc[mt][0] : r0;
            float zf = lo ? r0         : acc[mt][1];
            float zg = lo ? acc[mt][2] : r1;
            float zo = lo ? r1         : acc[mt][3];

            cst[mt] = sigfast(zf) * cst[mt] + sigfast(zi) * tanhfast(zg);
            float h = sigfast(zo) * tanhfast(cst[mt]);

            __half hh = __float2half_rn(h);
            hsh[(t + 1) & 1][ncol * HP1 + uu[mt]] = hh;
            hstage[t & 1][ncol * 128 + uu[mt]] = hh;
        }
        cp_wait0();
        __syncthreads();
    }
    // flush last step
    if (tid < 128) {
        int row = tid >> 4, ch = tid & 15;
        uint4 v = *(const uint4*)&hstage[(Tc - 1) & 1][row * 128 + ch * 8];
        *(uint4*)(hs1 + ((size_t)(b0 + row) * Tc + (Tc - 1)) * H1c + ch * 8) = v;
    }
}

// ---------------------------------------------------------------------------
// LSTM layer 2 (gate-permuted, fused input projection) + FC head.
// R11 delta: 3 independent MMA chains (bias+ih0-3 / ih4-7 / hh0-3).
// ---------------------------------------------------------------------------
__global__ void __launch_bounds__(512) lstm2_kernel(const __half* __restrict__ hs1,  // [B][T][128]
                                                    const float* __restrict__ Whh,   // [256][64]
                                                    const float* __restrict__ Wih,   // [256][128]
                                                    const float* __restrict__ b_ih,
                                                    const float* __restrict__ b_hh,
                                                    const float* __restrict__ fc1w,
                                                    const float* __restrict__ fc1b,
                                                    const float* __restrict__ fc2w,
                                                    const float* __restrict__ fc2b,
                                                    float* __restrict__ out)
{
    constexpr int HP = 72;
    constexpr int XP = 136;
    __shared__ __half hsh[2][8 * HP];
    __shared__ alignas(16) __half xb[2][8 * XP];
    __shared__ float hfin[8][64];

    const int tid  = threadIdx.x;
    const int w    = tid >> 5;
    const int lane = tid & 31;
    const int b0   = blockIdx.x * 8;
    const int r    = lane >> 2;
    const int q    = lane & 3;
    const int n0   = q * 2;
    const bool lo  = (r < 4);

    const int u   = w * 4 + (r & 3);
    const int Glo = (r >> 2) * H2c + u;
    const int Ghi = ((r + 8) >> 2) * H2c + u;

    uint32_t ahh[4][4];
    {
        const float* rl = Whh + (size_t)Glo * H2c;
        const float* rh = Whh + (size_t)Ghi * H2c;
#pragma unroll
        for (int ks = 0; ks < 4; ks++) {
            int k = ks * 16 + q * 2;
            ahh[ks][0] = packh2(rl[k],     rl[k + 1]);
            ahh[ks][1] = packh2(rh[k],     rh[k + 1]);
            ahh[ks][2] = packh2(rl[k + 8], rl[k + 9]);
            ahh[ks][3] = packh2(rh[k + 8], rh[k + 9]);
        }
    }
    uint32_t aih[8][4];
    {
        const float* rl = Wih + (size_t)Glo * H1c;
        const float* rh = Wih + (size_t)Ghi * H1c;
#pragma unroll
        for (int ks = 0; ks < 8; ks++) {
            int k = ks * 16 + q * 2;
            aih[ks][0] = packh2(rl[k],     rl[k + 1]);
            aih[ks][1] = packh2(rh[k],     rh[k + 1]);
            aih[ks][2] = packh2(rl[k + 8], rl[k + 9]);
            aih[ks][3] = packh2(rh[k + 8], rh[k + 9]);
        }
    }
    const float blo = __ldg(b_ih + Glo) + __ldg(b_hh + Glo);
    const float bhi = __ldg(b_ih + Ghi) + __ldg(b_hh + Ghi);

    for (int i = tid; i < 2 * 8 * HP / 2; i += 512)
        ((__half2*)hsh)[i] = __floats2half2_rn(0.f, 0.f);

    if (tid < 128) {
        int row = tid >> 4, ch = tid & 15;
        cp16(s2u(&xb[0][row * XP + ch * 8]),
             hs1 + ((size_t)(b0 + row) * Tc + 0) * H1c + ch * 8);
        cp_commit();
        cp_wait0();
    }
    __syncthreads();

    const int ncol = n0 + (lo ? 0 : 1);
    float cst = 0.f;

    for (int t = 0; t < Tc; t++) {
        if (tid < 128 && t + 1 < Tc) {
            int row = tid >> 4, ch = tid & 15;
            cp16(s2u(&xb[(t + 1) & 1][row * XP + ch * 8]),
                 hs1 + ((size_t)(b0 + row) * Tc + (t + 1)) * H1c + ch * 8);
            cp_commit();
        }

        const __half* x1 = xb[t & 1];
        const __half* hb = hsh[t & 1];
        const int l = lane & 15;

        uint32_t bh1[8][2];
        {
            uint32_t baddr = s2u(&x1[(l & 7) * XP + ((l >> 3) & 1) * 8]);
#pragma unroll
            for (int ks = 0; ks < 8; ks++)
                ldm_x2(bh1[ks][0], bh1[ks][1], baddr + ks * 32);
        }
        uint32_t bh2[4][2];
        {
            uint32_t baddr = s2u(&hb[(l & 7) * HP + ((l >> 3) & 1) * 8]);
#pragma unroll
            for (int ks = 0; ks < 4; ks++)
                ldm_x2(bh2[ks][0], bh2[ks][1], baddr + ks * 32);
        }

        float A[4] = {blo, blo, bhi, bhi};
        float B[4] = {0.f, 0.f, 0.f, 0.f};
        float C[4] = {0.f, 0.f, 0.f, 0.f};
#pragma unroll
        for (int ks = 0; ks < 4; ks++) {
            mma16816(A, aih[ks], bh1[ks]);
            mma16816(B, aih[ks + 4], bh1[ks + 4]);
            mma16816(C, ahh[ks], bh2[ks]);
        }
        float acc[4];
#pragma unroll
        for (int i = 0; i < 4; i++) acc[i] = A[i] + B[i] + C[i];

        float s0 = lo ? acc[1] : acc[0];
        float s1 = lo ? acc[3] : acc[2];
        float r0 = __shfl_xor_sync(0xffffffffu, s0, 16);
        float r1 = __shfl_xor_sync(0xffffffffu, s1, 16);
        float zi = lo ? acc[0] : r0;
        float zf = lo ? r0     : acc[1];
        float zg = lo ? acc[2] : r1;
        float zo = lo ? r1     : acc[3];

        cst = sigfast(zf) * cst + sigfast(zi) * tanhfast(zg);
        float h = sigfast(zo) * tanhfast(cst);

        hsh[(t + 1) & 1][ncol * HP + u] = __float2half_rn(h);
        if (t == Tc - 1) hfin[ncol][u] = h;

        if (tid < 128) cp_wait0();
        __syncthreads();
    }

    // FC head: warp w -> batch row w (warps 0..7), lane = fc1 unit
    if (w < 8) {
        float a = __ldg(fc1b + lane);
#pragma unroll
        for (int k = 0; k < 64; k++)
            a = fmaf(hfin[w][k], __ldg(fc1w + lane * 64 + k), a);
        a = fmaxf(a, 0.f);
        float v = a * __ldg(fc2w + lane);
#pragma unroll
        for (int off = 16; off; off >>= 1) v += __shfl_down_sync(0xffffffffu, v, off);
        if (lane == 0) out[b0 + w] = 1.f / (1.f + __expf(-(v + __ldg(fc2b))));
    }
}

// ---------------------------------------------------------------------------
extern "C" void kernel_launch(void* const* d_in, const int* in_sizes, int n_in,
                              void* d_out, int out_size)
{
    (void)in_sizes; (void)n_in; (void)out_size;
    const float* X     = (const float*)d_in[0];
    const float* W1_ih = (const float*)d_in[1];
    const float* W1_hh = (const float*)d_in[2];
    const float* b1_ih = (const float*)d_in[3];
    const float* b1_hh = (const float*)d_in[4];
    const float* W2_ih = (const float*)d_in[5];
    const float* W2_hh = (const float*)d_in[6];
    const float* b2_ih = (const float*)d_in[7];
    const float* b2_hh = (const float*)d_in[8];
    const float* fc1w  = (const float*)d_in[9];
    const float* fc1b  = (const float*)d_in[10];
    const float* fc2w  = (const float*)d_in[11];
    const float* fc2b  = (const float*)d_in[12];
    float* out = (float*)d_out;

    __half *xh, *w1h, *xw1, *hs1;
    cudaGetSymbolAddress((void**)&xh,  g_xh);
    cudaGetSymbolAddress((void**)&w1h, g_w1h);
    cudaGetSymbolAddress((void**)&xw1, g_xw1);
    cudaGetSymbolAddress((void**)&hs1, g_hs1);

    // 0) pad+convert X and W1_ih to fp16 [..][112]
    convert_pad<<<(Mtot * (KP / 2) + 255) / 256, 256>>>(X, xh, Mtot);
    convert_pad<<<(G1c * (KP / 2) + 255) / 256, 256>>>(W1_ih, w1h, G1c);
    // 1) xw1 = half(X @ W1_ih^T + b)   (all-fp16 single-K-tile GEMM)
    gemm1h<<<dim3(G1c / 128, Mtot / 128), 256>>>(xh, w1h, b1_ih, b1_hh, xw1);
    // 2) layer-1 recurrence (gate-permuted tensor-core)
    lstm1_kernel<<<Bc / 8, 512>>>(xw1, W1_hh, hs1);
    // 3) layer-2 recurrence (fused input projection) + FC head
    lstm2_kernel<<<Bc / 8, 512>>>(hs1, W2_hh, W2_ih, b2_ih, b2_hh,
                                  fc1w, fc1b, fc2w, fc2b, out);
}

// round 12
// speedup vs baseline: 3.1990x; 1.1524x over previous
#include <cuda_runtime.h>
#include <cuda_fp16.h>
#include <cstdint>

// Problem constants
#define Bc   1024
#define Tc   512
#define EMBc 100
#define KP   112   // padded K for layer-1 gemm (fp16, zero-filled)
#define H1c  128
#define G1c  512   // 4*H1
#define H2c  64
#define G2c  256   // 4*H2
#define Mtot (Bc*Tc)  // 524288

// Scratch (fp16)
__device__ __half g_xh [(size_t)Mtot * KP];   // padded fp16 X
__device__ __half g_w1h[(size_t)G1c * KP];    // padded fp16 W1_ih
__device__ __half g_xw1[(size_t)Mtot * G1c];  // layer-1 gate preactivations [b][t][512]

// ---------------------------------------------------------------------------
// helpers
// ---------------------------------------------------------------------------
__device__ __forceinline__ uint32_t s2u(const void* p) {
    return (uint32_t)__cvta_generic_to_shared(p);
}
__device__ __forceinline__ void ldm_x4(uint32_t& a0, uint32_t& a1, uint32_t& a2, uint32_t& a3,
                                       uint32_t addr) {
    asm volatile("ldmatrix.sync.aligned.m8n8.x4.shared.b16 {%0,%1,%2,%3}, [%4];"
                 : "=r"(a0), "=r"(a1), "=r"(a2), "=r"(a3) : "r"(addr));
}
__device__ __forceinline__ void ldm_x2(uint32_t& b0, uint32_t& b1, uint32_t addr) {
    asm volatile("ldmatrix.sync.aligned.m8n8.x2.shared.b16 {%0,%1}, [%2];"
                 : "=r"(b0), "=r"(b1) : "r"(addr));
}
__device__ __forceinline__ void mma16816(float* d, const uint32_t* a, const uint32_t* b) {
    asm volatile("mma.sync.aligned.m16n8k16.row.col.f32.f16.f16.f32 "
                 "{%0,%1,%2,%3}, {%4,%5,%6,%7}, {%8,%9}, {%0,%1,%2,%3};"
                 : "+f"(d[0]), "+f"(d[1]), "+f"(d[2]), "+f"(d[3])
                 : "r"(a[0]), "r"(a[1]), "r"(a[2]), "r"(a[3]), "r"(b[0]), "r"(b[1]));
}
__device__ __forceinline__ float tanhfast(float x) {
    float y;
    asm("tanh.approx.f32 %0, %1;" : "=f"(y) : "f"(x));
    return y;
}
__device__ __forceinline__ float sigfast(float x) {
    return 0.5f * tanhfast(0.5f * x) + 0.5f;
}
__device__ __forceinline__ uint32_t packh2(float x, float y) {
    __half2 h = __floats2half2_rn(x, y);
    return *reinterpret_cast<uint32_t*>(&h);
}
__device__ __forceinline__ void cp16(uint32_t smem_addr, const void* gptr) {
    asm volatile("cp.async.cg.shared.global [%0], [%1], 16;" :: "r"(smem_addr), "l"(gptr));
}
__device__ __forceinline__ void cp_commit() { asm volatile("cp.async.commit_group;"); }
__device__ __forceinline__ void cp_wait0()  { asm volatile("cp.async.wait_group 0;"); }

// ---------------------------------------------------------------------------
// fp32 [rows][EMBc] -> fp16 [rows][KP], zero-padded.
// ---------------------------------------------------------------------------
__global__ void convert_pad(const float* __restrict__ src, __half* __restrict__ dst, int rows)
{
    int gid = blockIdx.x * blockDim.x + threadIdx.x;
    int total = rows * (KP / 2);
    if (gid >= total) return;
    int row = gid / (KP / 2);
    int p   = gid - row * (KP / 2);
    int k   = 2 * p;
    float x0 = (k < EMBc)     ? src[(size_t)row * EMBc + k]     : 0.f;
    float x1 = (k + 1 < EMBc) ? src[(size_t)row * EMBc + k + 1] : 0.f;
    *(__half2*)(dst + (size_t)row * KP + k) = __floats2half2_rn(x0, x1);
}

// ---------------------------------------------------------------------------
// Layer-1 GEMM (known-good): fp16 in / fp16 out, K=112 single smem tile.
// ---------------------------------------------------------------------------
__global__ void __launch_bounds__(256) gemm1h(const __half* __restrict__ A,   // [M][112]
                                              const __half* __restrict__ W,   // [512][112]
                                              const float* __restrict__ ba,
                                              const float* __restrict__ bb,
                                              __half* __restrict__ out)
{
    constexpr int LDSs = 120;
    __shared__ alignas(16) __half As[128 * LDSs];
    __shared__ alignas(16) __half Ws[128 * LDSs];

    const int tid  = threadIdx.x;
    const int bm   = blockIdx.y * 128;
    const int bn   = blockIdx.x * 128;
    const int w    = tid >> 5;
    const int lane = tid & 31;
    const int wm   = (w >> 2) * 64;
    const int wn   = (w & 3) * 32;

    {
        const int m = tid >> 1;
#pragma unroll
        for (int c = 0; c < 7; c++) {
            int cc = c * 2 + (tid & 1);
            cp16(s2u(&As[m * LDSs + cc * 8]), A + (size_t)(bm + m) * KP + cc * 8);
            cp16(s2u(&Ws[m * LDSs + cc * 8]), W + (size_t)(bn + m) * KP + cc * 8);
        }
        cp_commit();
        cp_wait0();
    }
    __syncthreads();

    float acc[4][4][4];
#pragma unroll
    for (int mt = 0; mt < 4; mt++)
#pragma unroll
        for (int nt = 0; nt < 4; nt++)
#pragma unroll
            for (int i = 0; i < 4; i++) acc[mt][nt][i] = 0.f;

#pragma unroll
    for (int ks = 0; ks < 7; ks++) {
        uint32_t af[4][4];
#pragma unroll
        for (int mt = 0; mt < 4; mt++) {
            uint32_t addr = s2u(&As[(wm + mt * 16 + (lane & 15)) * LDSs + ks * 16 + (lane >> 4) * 8]);
            ldm_x4(af[mt][0], af[mt][1], af[mt][2], af[mt][3], addr);
        }
        uint32_t bf[4][2];
#pragma unroll
        for (int nt = 0; nt < 4; nt++) {
            int l = lane & 15;
            uint32_t addr = s2u(&Ws[(wn + nt * 8 + (l & 7)) * LDSs + ks * 16 + ((l >> 3) & 1) * 8]);
            ldm_x2(bf[nt][0], bf[nt][1], addr);
        }
#pragma unroll
        for (int mt = 0; mt < 4; mt++)
#pragma unroll
            for (int nt = 0; nt < 4; nt++)
                mma16816(acc[mt][nt], af[mt], bf[nt]);
    }

#pragma unroll
    for (int mt = 0; mt < 4; mt++) {
#pragma unroll
        for (int nt = 0; nt < 4; nt++) {
            int row = bm + wm + mt * 16 + (lane >> 2);
            int col = bn + wn + nt * 8 + (lane & 3) * 2;
            float b0 = __ldg(ba + col) + __ldg(bb + col);
            float b1 = __ldg(ba + col + 1) + __ldg(bb + col + 1);
            *(__half2*)(out + (size_t)row * G1c + col) =
                __floats2half2_rn(acc[mt][nt][0] + b0, acc[mt][nt][1] + b1);
            *(__half2*)(out + (size_t)(row + 8) * G1c + col) =
                __floats2half2_rn(acc[mt][nt][2] + b0, acc[mt][nt][3] + b1);
        }
    }
}

// ---------------------------------------------------------------------------
// FUSED layer-1 + layer-2 recurrence + FC head.
// At iteration t: compute h1[t] (L1, needs h1[t-1]) AND h2[t-1] (L2, needs
// h1[t-1] + h2[t-2]) — independent given iter t-1 state. bf1 fragments of
// h1[t-1] are shared by L1-hh and L2-ih MMAs. W1_hh persistent in registers;
// W2 weights in smem (permuted rows for direct ldm_x4 A-fragments).
// 128 blocks x 512 threads, 8 batch rows/block. hs1 never touches gmem.
// ---------------------------------------------------------------------------
#define HP1f 136
#define HP2f 72
#define XPf  520
#define WISf 136
#define WHSf 72
#define SM_WIH   (256 * WISf * 2)                  // 69632
#define SM_WHH   (256 * WHSf * 2)                  // 36864
#define SM_XWB   (2 * 8 * XPf * 2)                 // 16640
#define SM_HSH1  (2 * 8 * HP1f * 2)                // 4352
#define SM_HSH2  (2 * 8 * HP2f * 2)                // 2304
#define SM_HFIN  (8 * 64 * 4)                      // 2048
#define SMEMF (SM_WIH + SM_WHH + SM_XWB + SM_HSH1 + SM_HSH2 + SM_HFIN)

__global__ void __launch_bounds__(512) lstm12_kernel(
    const __half* __restrict__ xw,    // [B][T][512]
    const float* __restrict__ W1hh,   // [512][128]
    const float* __restrict__ W2ih,   // [256][128]
    const float* __restrict__ W2hh,   // [256][64]
    const float* __restrict__ b2_ih,
    const float* __restrict__ b2_hh,
    const float* __restrict__ fc1w,
    const float* __restrict__ fc1b,
    const float* __restrict__ fc2w,
    const float* __restrict__ fc2b,
    float* __restrict__ out)
{
    extern __shared__ char smraw[];
    __half* Wihs = (__half*)smraw;
    __half* Whhs = (__half*)(smraw + SM_WIH);
    __half* xwb  = (__half*)(smraw + SM_WIH + SM_WHH);
    __half* hsh1 = (__half*)(smraw + SM_WIH + SM_WHH + SM_XWB);
    __half* hsh2 = (__half*)(smraw + SM_WIH + SM_WHH + SM_XWB + SM_HSH1);
    float*  hfin = (float*)(smraw + SM_WIH + SM_WHH + SM_XWB + SM_HSH1 + SM_HSH2);

    const int tid  = threadIdx.x;
    const int w    = tid >> 5;
    const int lane = tid & 31;
    const int b0   = blockIdx.x * 8;
    const int r    = lane >> 2;
    const int q    = lane & 3;
    const int n0   = q * 2;
    const bool lo  = (r < 4);
    const int ncol = n0 + (lo ? 0 : 1);

    // ---- L1 mapping (16 warps x 2 m16 tiles, gate-permuted) ----
    int uu[2], Glo1[2], Ghi1[2];
#pragma unroll
    for (int mt = 0; mt < 2; mt++) {
        uu[mt]   = w * 8 + mt * 4 + (r & 3);
        Glo1[mt] = (r >> 2) * H1c + uu[mt];
        Ghi1[mt] = ((r + 8) >> 2) * H1c + uu[mt];
    }
    // persistent W1_hh fragments
    uint32_t afr[2][8][4];
#pragma unroll
    for (int mt = 0; mt < 2; mt++) {
        const float* rl = W1hh + (size_t)Glo1[mt] * H1c;
        const float* rh = W1hh + (size_t)Ghi1[mt] * H1c;
#pragma unroll
        for (int ks = 0; ks < 8; ks++) {
            int k = ks * 16 + q * 2;
            afr[mt][ks][0] = packh2(rl[k],     rl[k + 1]);
            afr[mt][ks][1] = packh2(rh[k],     rh[k + 1]);
            afr[mt][ks][2] = packh2(rl[k + 8], rl[k + 9]);
            afr[mt][ks][3] = packh2(rh[k + 8], rh[k + 9]);
        }
    }

    // ---- L2 mapping (16 warps x 1 m16 tile) ----
    const int u    = w * 4 + (r & 3);
    const int Glo2 = (r >> 2) * H2c + u;
    const int Ghi2 = ((r + 8) >> 2) * H2c + u;
    const float blo = __ldg(b2_ih + Glo2) + __ldg(b2_hh + Glo2);
    const float bhi = __ldg(b2_ih + Ghi2) + __ldg(b2_hh + Ghi2);

    // ---- stage W2 into smem, PERMUTED rows: tr -> src gate-unit row ----
    for (int idx = tid; idx < 256 * 128; idx += 512) {
        int tr = idx >> 7, k = idx & 127;
        int pr = tr & 15, ww = tr >> 4;
        int src = (pr >> 2) * 64 + ww * 4 + (pr & 3);
        Wihs[tr * WISf + k] = __float2half_rn(W2ih[(size_t)src * 128 + k]);
    }
    for (int idx = tid; idx < 256 * 64; idx += 512) {
        int tr = idx >> 6, k = idx & 63;
        int pr = tr & 15, ww = tr >> 4;
        int src = (pr >> 2) * 64 + ww * 4 + (pr & 3);
        Whhs[tr * WHSf + k] = __float2half_rn(W2hh[(size_t)src * 64 + k]);
    }

    // zero h states (both buffers)
    for (int i = tid; i < 2 * 8 * HP1f / 2; i += 512)
        ((__half2*)hsh1)[i] = __floats2half2_rn(0.f, 0.f);
    for (int i = tid; i < 2 * 8 * HP2f / 2; i += 512)
        ((__half2*)hsh2)[i] = __floats2half2_rn(0.f, 0.f);

    // prefetch xw tile for t=0 (8 rows x 64 16B chunks = 512 threads x 16B)
    {
        int row = tid >> 6, ch = tid & 63;
        cp16(s2u(&xwb[0 * 8 * XPf + row * XPf + ch * 8]),
             xw + ((size_t)(b0 + row) * Tc + 0) * G1c + ch * 8);
        cp_commit();
        cp_wait0();
    }
    __syncthreads();

    // precomputed smem byte-addresses for L2 A-frag ldm_x4
    const uint32_t aih_base = s2u(Wihs + (w * 16 + (lane & 15)) * WISf + (lane >> 4) * 8);
    const uint32_t ahh_base = s2u(Whhs + (w * 16 + (lane & 15)) * WHSf + (lane >> 4) * 8);

    float cst1[2] = {0.f, 0.f};
    float cst2 = 0.f;

    for (int t = 0; t <= Tc; t++) {
        if (t + 1 < Tc) {
            int row = tid >> 6, ch = tid & 63;
            cp16(s2u(&xwb[((t + 1) & 1) * 8 * XPf + row * XPf + ch * 8]),
                 xw + ((size_t)(b0 + row) * Tc + (t + 1)) * G1c + ch * 8);
            cp_commit();
        }

        const __half* xb  = xwb + (t & 1) * 8 * XPf;
        const __half* hb1 = hsh1 + (t & 1) * 8 * HP1f;
        const __half* hb2 = hsh2 + (t & 1) * 8 * HP2f;
        const int l = lane & 15;

        // B fragments of h1[t-1] — shared by L1-hh and L2-ih MMAs
        uint32_t bf1[8][2];
        {
            uint32_t baddr = s2u(hb1 + (l & 7) * HP1f + ((l >> 3) & 1) * 8);
#pragma unroll
            for (int ks = 0; ks < 8; ks++)
                ldm_x2(bf1[ks][0], bf1[ks][1], baddr + ks * 32);
        }
        // B fragments of h2[t-2]
        uint32_t bf2[4][2];
        {
            uint32_t baddr = s2u(hb2 + (l & 7) * HP2f + ((l >> 3) & 1) * 8);
#pragma unroll
            for (int ks = 0; ks < 4; ks++)
                ldm_x2(bf2[ks][0], bf2[ks][1], baddr + ks * 32);
        }

        // ---- L1: h1[t] ----
        if (t < Tc) {
            float acc1[2][4];
            acc1[0][0] = __half2float(xb[n0 * XPf + Glo1[0]]);
            acc1[0][1] = __half2float(xb[(n0 + 1) * XPf + Glo1[0]]);
            acc1[0][2] = __half2float(xb[n0 * XPf + Ghi1[0]]);
            acc1[0][3] = __half2float(xb[(n0 + 1) * XPf + Ghi1[0]]);
            acc1[1][0] = __half2float(xb[n0 * XPf + Glo1[1]]);
            acc1[1][1] = __half2float(xb[(n0 + 1) * XPf + Glo1[1]]);
            acc1[1][2] = __half2float(xb[n0 * XPf + Ghi1[1]]);
            acc1[1][3] = __half2float(xb[(n0 + 1) * XPf + Ghi1[1]]);
#pragma unroll
            for (int ks = 0; ks < 8; ks++) {
                mma16816(acc1[0], afr[0][ks], bf1[ks]);
                mma16816(acc1[1], afr[1][ks], bf1[ks]);
            }
#pragma unroll
            for (int mt = 0; mt < 2; mt++) {
                float s0 = lo ? acc1[mt][1] : acc1[mt][0];
                float s1 = lo ? acc1[mt][3] : acc1[mt][2];
                float r0 = __shfl_xor_sync(0xffffffffu, s0, 16);
                float r1 = __shfl_xor_sync(0xffffffffu, s1, 16);
                float zi = lo ? acc1[mt][0] : r0;
                float zf = lo ? r0          : acc1[mt][1];
                float zg = lo ? acc1[mt][2] : r1;
                float zo = lo ? r1          : acc1[mt][3];

                cst1[mt] = sigfast(zf) * cst1[mt] + sigfast(zi) * tanhfast(zg);
                float h = sigfast(zo) * tanhfast(cst1[mt]);
                hsh1[((t + 1) & 1) * 8 * HP1f + ncol * HP1f + uu[mt]] = __float2half_rn(h);
            }
        }

        // ---- L2: h2[t-1] ----
        if (t >= 1) {
            float accA[4] = {blo, blo, bhi, bhi};
            float accC[4] = {0.f, 0.f, 0.f, 0.f};
#pragma unroll
            for (int ks = 0; ks < 8; ks++) {
                uint32_t a2[4];
                ldm_x4(a2[0], a2[1], a2[2], a2[3], aih_base + ks * 32);
                mma16816(accA, a2, bf1[ks]);
            }
#pragma unroll
            for (int ks = 0; ks < 4; ks++) {
                uint32_t a2[4];
                ldm_x4(a2[0], a2[1], a2[2], a2[3], ahh_base + ks * 32);
                mma16816(accC, a2, bf2[ks]);
            }
            float acc[4];
#pragma unroll
            for (int i = 0; i < 4; i++) acc[i] = accA[i] + accC[i];

            float s0 = lo ? acc[1] : acc[0];
            float s1 = lo ? acc[3] : acc[2];
            float r0 = __shfl_xor_sync(0xffffffffu, s0, 16);
            float r1 = __shfl_xor_sync(0xffffffffu, s1, 16);
            float zi = lo ? acc[0] : r0;
            float zf = lo ? r0     : acc[1];
            float zg = lo ? acc[2] : r1;
            float zo = lo ? r1     : acc[3];

            cst2 = sigfast(zf) * cst2 + sigfast(zi) * tanhfast(zg);
            float h = sigfast(zo) * tanhfast(cst2);

            if (t == Tc) hfin[ncol * 64 + u] = h;
            else hsh2[((t + 1) & 1) * 8 * HP2f + ncol * HP2f + u] = __float2half_rn(h);
        }

        cp_wait0();
        __syncthreads();
    }

    // FC head: warp w -> batch row w (warps 0..7), lane = fc1 unit
    if (w < 8) {
        float a = __ldg(fc1b + lane);
#pragma unroll
        for (int k = 0; k < 64; k++)
            a = fmaf(hfin[w * 64 + k], __ldg(fc1w + lane * 64 + k), a);
        a = fmaxf(a, 0.f);
        float v = a * __ldg(fc2w + lane);
#pragma unroll
        for (int off = 16; off; off >>= 1) v += __shfl_down_sync(0xffffffffu, v, off);
        if (lane == 0) out[b0 + w] = 1.f / (1.f + __expf(-(v + __ldg(fc2b))));
    }
}

// ---------------------------------------------------------------------------
extern "C" void kernel_launch(void* const* d_in, const int* in_sizes, int n_in,
                              void* d_out, int out_size)
{
    (void)in_sizes; (void)n_in; (void)out_size;
    const float* X     = (const float*)d_in[0];
    const float* W1_ih = (const float*)d_in[1];
    const float* W1_hh = (const float*)d_in[2];
    const float* b1_ih = (const float*)d_in[3];
    const float* b1_hh = (const float*)d_in[4];
    const float* W2_ih = (const float*)d_in[5];
    const float* W2_hh = (const float*)d_in[6];
    const float* b2_ih = (const float*)d_in[7];
    const float* b2_hh = (const float*)d_in[8];
    const float* fc1w  = (const float*)d_in[9];
    const float* fc1b  = (const float*)d_in[10];
    const float* fc2w  = (const float*)d_in[11];
    const float* fc2b  = (const float*)d_in[12];
    float* out = (float*)d_out;

    __half *xh, *w1h, *xw1;
    cudaGetSymbolAddress((void**)&xh,  g_xh);
    cudaGetSymbolAddress((void**)&w1h, g_w1h);
    cudaGetSymbolAddress((void**)&xw1, g_xw1);

    static int attr_done = 0;
    if (!attr_done) {
        cudaFuncSetAttribute(lstm12_kernel, cudaFuncAttributeMaxDynamicSharedMemorySize, SMEMF);
        attr_done = 1;
    }

    // 0) pad+convert X and W1_ih to fp16 [..][112]
    convert_pad<<<(Mtot * (KP / 2) + 255) / 256, 256>>>(X, xh, Mtot);
    convert_pad<<<(G1c * (KP / 2) + 255) / 256, 256>>>(W1_ih, w1h, G1c);
    // 1) xw1 = half(X @ W1_ih^T + b)
    gemm1h<<<dim3(G1c / 128, Mtot / 128), 256>>>(xh, w1h, b1_ih, b1_hh, xw1);
    // 2) fused layer-1 + layer-2 recurrence + FC head
    lstm12_kernel<<<Bc / 8, 512, SMEMF>>>(xw1, W1_hh, W2_ih, W2_hh, b2_ih, b2_hh,
                                          fc1w, fc1b, fc2w, fc2b, out);
}